// round 11
// baseline (speedup 1.0000x reference)
#include <cuda_runtime.h>
#include <cuda_fp16.h>
#include <cstdint>
#include <math.h>

#define BBATCH 128
#define TLEN   500
#define NLAB   35
#define FSZ    (128*500*128)     // [b][t][c] feature tensor
#define NELEM  64000.0f
#define BN_EPS 1e-5f

// ---------- device scratch ----------
__device__ __half g_X[FSZ];
__device__ float  g_Z[FSZ];      // ODE state stays fp32
__device__ float  g_ZA[FSZ];
__device__ __half g_K[FSZ];
__device__ __half g_Y1[FSZ];
__device__ __half g_Y2[FSZ];
__device__ __half g_Y3[FSZ];

// fp16 weight images: [tap][128 co][136 ci]
__device__ __half g_W0p[3*128*136];
__device__ __half g_W1p[9*128*136];
__device__ __half g_W2p[9*128*136];
__device__ __half g_W3p[1*128*136];

// per-conv-instance BN stat slots: [slot][0:128)=sum, [128:256)=ssq
#define NSLOTS 50
__device__ float g_stats[NSLOTS*256];

// ---------- helpers ----------
__device__ __forceinline__ uint32_t smem_u32(const void* p) {
    uint32_t a;
    asm("{ .reg .u64 t; cvta.to.shared.u64 t, %1; cvt.u32.u64 %0, t; }" : "=r"(a) : "l"(p));
    return a;
}
__device__ __forceinline__ void cp_async16(uint32_t dst, const void* src) {
    asm volatile("cp.async.cg.shared.global [%0], [%1], 16;" :: "r"(dst), "l"(src));
}
#define CP_COMMIT() asm volatile("cp.async.commit_group;" ::: "memory")
#define CP_WAIT(n)  asm volatile("cp.async.wait_group %0;" :: "n"(n) : "memory")

__device__ __forceinline__ void ldsm_x4(uint32_t* r, uint32_t addr) {
    asm volatile("ldmatrix.sync.aligned.m8n8.x4.shared.b16 {%0,%1,%2,%3}, [%4];"
        : "=r"(r[0]), "=r"(r[1]), "=r"(r[2]), "=r"(r[3]) : "r"(addr));
}
__device__ __forceinline__ void mma_f16(float* d, const uint32_t* a, uint32_t b0, uint32_t b1) {
    asm volatile("mma.sync.aligned.m16n8k16.row.col.f32.f16.f16.f32 "
        "{%0,%1,%2,%3}, {%4,%5,%6,%7}, {%8,%9}, {%0,%1,%2,%3};"
        : "+f"(d[0]), "+f"(d[1]), "+f"(d[2]), "+f"(d[3])
        : "r"(a[0]), "r"(a[1]), "r"(a[2]), "r"(a[3]), "r"(b0), "r"(b1));
}

// ---------- small kernels ----------
__global__ void init_stats_kernel() {
    g_stats[blockIdx.x * 256 + threadIdx.x] = 0.f;
}

// src [128 co][CIR][NK] -> img [tap][co][136] fp16
__global__ void prep_w_kernel(const float* __restrict__ src, __half* __restrict__ img,
                              int CIR, int NK) {
    int idx = blockIdx.x * 256 + threadIdx.x;
    int tot = NK * 128 * 136;
    if (idx >= tot) return;
    int tap = idx / (128 * 136);
    int rem = idx - tap * 128 * 136;
    int co = rem / 136, ci = rem - co * 136;
    float v = (ci < CIR) ? src[(co * CIR + ci) * NK + tap] : 0.f;
    img[idx] = __float2half_rn(v);
}

// x[b][80][500] -> X[b][t][c] fp16
__global__ void xpose_kernel(const float* __restrict__ x, __half* __restrict__ X) {
    int i = blockIdx.x * 256 + threadIdx.x;
    if (i >= FSZ) return;
    int c = i & 127, bt = i >> 7;
    int t = bt % TLEN, b = bt / TLEN;
    X[i] = __float2half_rn((c < 80) ? x[(b * 80 + c) * TLEN + t] : 0.f);
}

// Z = relu(bn(Y1))  (Y1 fp16 -> Z fp32)
__global__ void bn_relu_kernel(const __half* __restrict__ Y, const float* __restrict__ bns,
                               float* __restrict__ Z) {
    __shared__ float ms[128], rs[128];
    int tid = threadIdx.x;
    if (tid < 128) {
        float m = bns[tid] * (1.f / NELEM);
        float v = bns[128 + tid] * (1.f / NELEM) - m * m;
        ms[tid] = m; rs[tid] = rsqrtf(v + BN_EPS);
    }
    __syncthreads();
    int i4 = blockIdx.x * 256 + tid;
    if (i4 * 4 >= FSZ) return;
    int c0 = (i4 * 4) & 127;
    __half2 ya = ((const __half2*)Y)[i4 * 2];
    __half2 yb = ((const __half2*)Y)[i4 * 2 + 1];
    float4 o;
    o.x = fmaxf((__low2float(ya)  - ms[c0])   * rs[c0],   0.f);
    o.y = fmaxf((__high2float(ya) - ms[c0+1]) * rs[c0+1], 0.f);
    o.z = fmaxf((__low2float(yb)  - ms[c0+2]) * rs[c0+2], 0.f);
    o.w = fmaxf((__high2float(yb) - ms[c0+3]) * rs[c0+3], 0.f);
    ((float4*)Z)[i4] = o;
}

// k = relu(bn(Y2) + relu(bn(Y3)));  K = k (fp16);  RK4 accumulator update (fp32)
__global__ void combine_kernel(const __half* __restrict__ Y2, const __half* __restrict__ Y3,
                               const float* __restrict__ bns2, const float* __restrict__ bns3,
                               const float* __restrict__ Z, __half* __restrict__ K,
                               float* __restrict__ ZA, float* __restrict__ Zout,
                               float wgt, int mode) {
    __shared__ float m2s[128], r2s[128], m3s[128], r3s[128];
    int tid = threadIdx.x;
    if (tid < 128) {
        float m = bns2[tid] * (1.f / NELEM);
        float v = bns2[128 + tid] * (1.f / NELEM) - m * m;
        m2s[tid] = m; r2s[tid] = rsqrtf(v + BN_EPS);
        m = bns3[tid] * (1.f / NELEM);
        v = bns3[128 + tid] * (1.f / NELEM) - m * m;
        m3s[tid] = m; r3s[tid] = rsqrtf(v + BN_EPS);
    }
    __syncthreads();
    int i4 = blockIdx.x * 256 + tid;
    if (i4 * 4 >= FSZ) return;
    int c0 = (i4 * 4) & 127;
    __half2 y2a = ((const __half2*)Y2)[i4 * 2];
    __half2 y2b = ((const __half2*)Y2)[i4 * 2 + 1];
    __half2 y3a = ((const __half2*)Y3)[i4 * 2];
    __half2 y3b = ((const __half2*)Y3)[i4 * 2 + 1];
    float k0, k1, k2, k3;
    {
        float a;
        a  = fmaxf((__low2float(y3a)  - m3s[c0])   * r3s[c0],   0.f);
        k0 = fmaxf((__low2float(y2a)  - m2s[c0])   * r2s[c0] + a, 0.f);
        a  = fmaxf((__high2float(y3a) - m3s[c0+1]) * r3s[c0+1], 0.f);
        k1 = fmaxf((__high2float(y2a) - m2s[c0+1]) * r2s[c0+1] + a, 0.f);
        a  = fmaxf((__low2float(y3b)  - m3s[c0+2]) * r3s[c0+2], 0.f);
        k2 = fmaxf((__low2float(y2b)  - m2s[c0+2]) * r2s[c0+2] + a, 0.f);
        a  = fmaxf((__high2float(y3b) - m3s[c0+3]) * r3s[c0+3], 0.f);
        k3 = fmaxf((__high2float(y2b) - m2s[c0+3]) * r2s[c0+3] + a, 0.f);
    }
    ((__half2*)K)[i4 * 2]     = __floats2half2_rn(k0, k1);
    ((__half2*)K)[i4 * 2 + 1] = __floats2half2_rn(k2, k3);
    float4 base;
    if (mode == 0) base = ((const float4*)Z)[i4];
    else           base = ((const float4*)ZA)[i4];
    float4 o;
    o.x = base.x + wgt * k0; o.y = base.y + wgt * k1;
    o.z = base.z + wgt * k2; o.w = base.w + wgt * k3;
    if (mode == 2) ((float4*)Zout)[i4] = o;
    else           ((float4*)ZA)[i4] = o;
}

__global__ void pool_head_kernel(const float* __restrict__ Z, const float* __restrict__ ow,
                                 const float* __restrict__ ob, float* __restrict__ out) {
    __shared__ float feat[128];
    int b = blockIdx.x, c = threadIdx.x;
    float s = 0.f;
    for (int t = 0; t < TLEN; t++) s += Z[((b * TLEN + t) << 7) + c];
    feat[c] = s * (1.0f / (float)TLEN);
    __syncthreads();
    if (c < NLAB) {
        float o = ob[c];
        for (int k = 0; k < 128; k++) o = fmaf(feat[k], ow[c * 128 + k], o);
        out[b * NLAB + c] = o;
    }
}

// ---------- mma.sync fp16 conv kernel ----------
#define NB      136
#define ROWB    272
#define B_OFF   0
#define A_OFF   (NB*ROWB)            // 36992
#define A_TAPB  34816                // 128 rows x 272
#define SM_STAT (A_OFF + 2*A_TAPB)   // 106624
#define SMEM_SZ (SM_STAT + 1024)     // 107648
#define A_CHUNKS (A_TAPB/16)         // 2176

// epilogue: frags -> Ts (A-buf0, two 64-row passes) -> coalesced half2 stores + stat atomics
__device__ __forceinline__ void epilogue_store(
    char* smem, float acc[4][4][4], int co_w, int t_w, int g, int tq,
    int tid, int b, int t0, __half* __restrict__ out, float* __restrict__ stat) {
    float* Ts = (float*)(smem + A_OFF);
    const int c2 = tid & 63;           // channel pair
    const int ph = tid >> 6;           // phase 0..3
    float s0 = 0.f, q0 = 0.f, s1 = 0.f, q1 = 0.f;
#pragma unroll
    for (int p = 0; p < 2; p++) {
        __syncthreads();
        if ((t_w >> 6) == p) {
#pragma unroll
            for (int mt = 0; mt < 4; mt++)
#pragma unroll
                for (int nt = 0; nt < 4; nt++) {
                    int co = co_w + mt * 16 + g;
                    int t  = (t_w & 63) + nt * 8 + tq * 2;
                    Ts[t * 132 + co]           = acc[mt][nt][0];
                    Ts[(t + 1) * 132 + co]     = acc[mt][nt][1];
                    Ts[t * 132 + co + 8]       = acc[mt][nt][2];
                    Ts[(t + 1) * 132 + co + 8] = acc[mt][nt][3];
                }
        }
        __syncthreads();
        for (int tl = ph; tl < 64; tl += 4) {
            int tt = p * 64 + tl;
            if (tt < 125) {
                float v0 = Ts[tl * 132 + c2 * 2];
                float v1 = Ts[tl * 132 + c2 * 2 + 1];
                s0 += v0; q0 += v0 * v0;
                s1 += v1; q1 += v1 * v1;
                ((__half2*)(out + ((b * TLEN + t0 + tt) << 7)))[c2] = __floats2half2_rn(v0, v1);
            }
        }
    }
    atomicAdd(&stat[c2 * 2], s0);
    atomicAdd(&stat[128 + c2 * 2], q0);
    atomicAdd(&stat[c2 * 2 + 1], s1);
    atomicAdd(&stat[128 + c2 * 2 + 1], q1);
}

// CTA: batch b, 128 co x 125 t. B smem: 136 rows x 128 ci fp16 (row 272B).
// Staging: base = in (fp32 if !INHALF, fp16 if INHALF); bnsA -> relu(bn(base));
// in2 (fp16 K) -> base += alpha*in2. FUSE3: second 1x1 conv sharing staged B.
template <int NTAPS, bool FUSE3, bool INHALF>
__global__ __launch_bounds__(256, 2)
void conv_mma_kernel(const void* __restrict__ inv,
                     const __half* __restrict__ in2, float alpha,
                     const __half* __restrict__ wimg, const __half* __restrict__ w3img,
                     const float* __restrict__ bnsA,
                     __half* __restrict__ out, float* __restrict__ stat,
                     __half* __restrict__ out3, float* __restrict__ stat3) {
    constexpr int R = NTAPS / 2;
    extern __shared__ char smem[];
    const uint32_t sb = smem_u32(smem);
    const int tid = threadIdx.x;
    const int t0 = blockIdx.x * 125;
    const int b  = blockIdx.y;

    const bool hbn = (bnsA != nullptr), h2 = (in2 != nullptr);

    float* smA_m = (float*)(smem + SM_STAT);
    float* smA_r = smA_m + 128;
    if (hbn) {
        if (tid < 128) {
            float m = bnsA[tid] * (1.f / NELEM);
            float v = bnsA[128 + tid] * (1.f / NELEM) - m * m;
            smA_m[tid] = m; smA_r[tid] = rsqrtf(v + BN_EPS);
        }
        __syncthreads();
    }

    // ---- stage B ----
    for (int idx = tid; idx < NB * 64; idx += 256) {
        int j = idx >> 6, pr = idx & 63;
        int u = t0 - R + j;
        float v0 = 0.f, v1 = 0.f;
        if (u >= 0 && u < TLEN) {
            int off = ((b * TLEN + u) << 7) + pr * 2;
            if (INHALF) {
                __half2 h = *(const __half2*)((const __half*)inv + off);
                v0 = __low2float(h); v1 = __high2float(h);
            } else {
                const float* p = (const float*)inv + off;
                v0 = p[0]; v1 = p[1];
            }
            int c = pr * 2;
            if (hbn) {
                v0 = fmaxf((v0 - smA_m[c]) * smA_r[c], 0.f);
                v1 = fmaxf((v1 - smA_m[c + 1]) * smA_r[c + 1], 0.f);
            }
            if (h2) {
                __half2 kk = *(const __half2*)(in2 + off);
                v0 += alpha * __low2float(kk);
                v1 += alpha * __high2float(kk);
            }
        }
        *(__half2*)(smem + B_OFF + j * ROWB + pr * 4) = __floats2half2_rn(v0, v1);
    }

    // ---- prefetch A tap 0 ----
    for (int i = tid; i < A_CHUNKS; i += 256)
        cp_async16(sb + A_OFF + i * 16, (const char*)wimg + i * 16);
    CP_COMMIT();
    __syncthreads();

    const int wid = tid >> 5, lane = tid & 31;
    const int co_w = (wid & 1) * 64;
    const int t_w  = (wid >> 1) * 32;
    const int g  = lane >> 2;
    const int tq = lane & 3;
    const int a_row = lane & 15;
    const int a_kh  = (lane >> 4) * 16;
    const int quad = lane >> 3;
    const int b_nl = (lane & 7) + ((quad >> 1) * 8);
    const int b_kh = (quad & 1) * 16;

    float acc[4][4][4];
#pragma unroll
    for (int mt = 0; mt < 4; mt++)
#pragma unroll
        for (int nt = 0; nt < 4; nt++)
#pragma unroll
            for (int e = 0; e < 4; e++) acc[mt][nt][e] = 0.f;

#pragma unroll 1
    for (int tap = 0; tap < NTAPS; tap++) {
        const int buf = tap & 1;
        if (tap + 1 < NTAPS) {
            const char* src = (const char*)wimg + (size_t)(tap + 1) * A_TAPB;
            uint32_t dst = sb + A_OFF + ((tap + 1) & 1) * A_TAPB;
            for (int i = tid; i < A_CHUNKS; i += 256) cp_async16(dst + i * 16, src + i * 16);
            CP_COMMIT();
            CP_WAIT(1);
        } else {
            CP_WAIT(0);
        }
        __syncthreads();

        const uint32_t Ab = sb + A_OFF + buf * A_TAPB;
        const uint32_t Bb = sb + B_OFF + (t_w + tap + b_nl) * ROWB + b_kh;

#pragma unroll
        for (int kc = 0; kc < 8; kc++) {
            uint32_t af[4][4];
#pragma unroll
            for (int mt = 0; mt < 4; mt++)
                ldsm_x4(af[mt], Ab + (co_w + mt * 16 + a_row) * ROWB + kc * 32 + a_kh);
            uint32_t bf[2][4];
#pragma unroll
            for (int p = 0; p < 2; p++)
                ldsm_x4(bf[p], Bb + p * 16 * ROWB + kc * 32);
#pragma unroll
            for (int mt = 0; mt < 4; mt++)
#pragma unroll
                for (int nt = 0; nt < 4; nt++)
                    mma_f16(acc[mt][nt], af[mt], bf[nt >> 1][(nt & 1) * 2], bf[nt >> 1][(nt & 1) * 2 + 1]);
        }
        __syncthreads();
    }

    if (FUSE3) {
        for (int i = tid; i < A_CHUNKS; i += 256)
            cp_async16(sb + A_OFF + A_TAPB + i * 16, (const char*)w3img + i * 16);
        CP_COMMIT();
    }

    epilogue_store(smem, acc, co_w, t_w, g, tq, tid, b, t0, out, stat);

    if (FUSE3) {
        CP_WAIT(0);
        __syncthreads();
#pragma unroll
        for (int mt = 0; mt < 4; mt++)
#pragma unroll
            for (int nt = 0; nt < 4; nt++)
#pragma unroll
                for (int e = 0; e < 4; e++) acc[mt][nt][e] = 0.f;

        const uint32_t Ab = sb + A_OFF + A_TAPB;
        const uint32_t Bb = sb + B_OFF + (t_w + R + b_nl) * ROWB + b_kh;
#pragma unroll
        for (int kc = 0; kc < 8; kc++) {
            uint32_t af[4][4];
#pragma unroll
            for (int mt = 0; mt < 4; mt++)
                ldsm_x4(af[mt], Ab + (co_w + mt * 16 + a_row) * ROWB + kc * 32 + a_kh);
            uint32_t bf[2][4];
#pragma unroll
            for (int p = 0; p < 2; p++)
                ldsm_x4(bf[p], Bb + p * 16 * ROWB + kc * 32);
#pragma unroll
            for (int mt = 0; mt < 4; mt++)
#pragma unroll
                for (int nt = 0; nt < 4; nt++)
                    mma_f16(acc[mt][nt], af[mt], bf[nt >> 1][(nt & 1) * 2], bf[nt >> 1][(nt & 1) * 2 + 1]);
        }
        epilogue_store(smem, acc, co_w, t_w, g, tq, tid, b, t0, out3, stat3);
    }
}

// ---------- launch ----------
extern "C" void kernel_launch(void* const* d_in, const int* in_sizes, int n_in,
                              void* d_out, int out_size) {
    const float* x  = (const float*)d_in[0];
    const float* w0 = (const float*)d_in[1];
    const float* w1 = (const float*)d_in[2];
    const float* w2 = (const float*)d_in[3];
    const float* w3 = (const float*)d_in[4];
    const float* ow = (const float*)d_in[5];
    const float* ob = (const float*)d_in[6];
    float* out = (float*)d_out;

    cudaFuncSetAttribute(conv_mma_kernel<9, true,  false>, cudaFuncAttributeMaxDynamicSharedMemorySize, SMEM_SZ);
    cudaFuncSetAttribute(conv_mma_kernel<9, false, true>,  cudaFuncAttributeMaxDynamicSharedMemorySize, SMEM_SZ);
    cudaFuncSetAttribute(conv_mma_kernel<3, false, true>,  cudaFuncAttributeMaxDynamicSharedMemorySize, SMEM_SZ);

    float *pZ, *pZA, *pS;
    __half *pX, *pK, *pY1, *pY2, *pY3;
    __half *pW0, *pW1, *pW2, *pW3;
    cudaGetSymbolAddress((void**)&pX,  g_X);
    cudaGetSymbolAddress((void**)&pZ,  g_Z);
    cudaGetSymbolAddress((void**)&pZA, g_ZA);
    cudaGetSymbolAddress((void**)&pK,  g_K);
    cudaGetSymbolAddress((void**)&pY1, g_Y1);
    cudaGetSymbolAddress((void**)&pY2, g_Y2);
    cudaGetSymbolAddress((void**)&pY3, g_Y3);
    cudaGetSymbolAddress((void**)&pW0, g_W0p);
    cudaGetSymbolAddress((void**)&pW1, g_W1p);
    cudaGetSymbolAddress((void**)&pW2, g_W2p);
    cudaGetSymbolAddress((void**)&pW3, g_W3p);
    cudaGetSymbolAddress((void**)&pS,  g_stats);

    const float dt = 0.25f;
    dim3 cgrid(4, 128);
    const int EW = (FSZ + 255) / 256;
    const int EW4 = (FSZ / 4 + 255) / 256;

    init_stats_kernel<<<NSLOTS, 256>>>();
    prep_w_kernel<<<(3*128*136 + 255)/256, 256>>>(w0, pW0, 80, 3);
    prep_w_kernel<<<(9*128*136 + 255)/256, 256>>>(w1, pW1, 128, 9);
    prep_w_kernel<<<(9*128*136 + 255)/256, 256>>>(w2, pW2, 128, 9);
    prep_w_kernel<<<(1*128*136 + 255)/256, 256>>>(w3, pW3, 128, 1);
    xpose_kernel<<<EW, 256>>>(x, pX);

    // conv0 -> Y1 (+slot 0), then BN+relu -> Z
    conv_mma_kernel<3, false, true><<<cgrid, 256, SMEM_SZ>>>(pX, nullptr, 0.f, pW0, nullptr,
                                                             nullptr, pY1, pS, nullptr, nullptr);
    bn_relu_kernel<<<EW4, 256>>>(pY1, pS, pZ);

    for (int step = 0; step < 4; ++step) {
        for (int e = 0; e < 4; ++e) {
            float alpha = (e == 0) ? 0.f : (e == 3 ? dt : 0.5f * dt);
            const __half* in2 = (e == 0) ? nullptr : pK;
            int si = 1 + (step * 4 + e) * 3;
            float* slotA = pS + si * 256;        // conv1 (Y1) stats
            float* slotB = pS + (si + 1) * 256;  // conv3 (Y3) stats
            float* slotC = pS + (si + 2) * 256;  // conv2 (Y2) stats

            // fused conv1(9-tap) + conv3(1x1); staging b = Z + alpha*K
            conv_mma_kernel<9, true, false><<<cgrid, 256, SMEM_SZ>>>(pZ, in2, alpha, pW1, pW3,
                                                                     nullptr, pY1, slotA, pY3, slotB);
            // conv2; staging b = relu(bn(Y1)) via slotA
            conv_mma_kernel<9, false, true><<<cgrid, 256, SMEM_SZ>>>(pY1, nullptr, 0.f, pW2, nullptr,
                                                                     slotA, pY2, slotC, nullptr, nullptr);
            float wgt = (dt / 6.0f) * ((e == 0 || e == 3) ? 1.0f : 2.0f);
            int mode = (e == 0) ? 0 : (e == 3 ? 2 : 1);
            combine_kernel<<<EW4, 256>>>(pY2, pY3, slotC, slotB, pZ, pK, pZA, pZ, wgt, mode);
        }
    }

    pool_head_kernel<<<128, 128>>>(pZ, ow, ob, out);
}

// round 12
// speedup vs baseline: 1.1476x; 1.1476x over previous
#include <cuda_runtime.h>
#include <cuda_fp16.h>
#include <cstdint>
#include <math.h>

#define BBATCH 128
#define TLEN   500
#define NLAB   35
#define FSZ    (128*500*128)     // [b][t][c] feature tensor
#define NELEM  64000.0f
#define BN_EPS 1e-5f

// ---------- device scratch ----------
__device__ float g_X[FSZ];
__device__ float g_Z[FSZ];
__device__ float g_ZA[FSZ];
__device__ float g_K[FSZ];
__device__ float g_Y1[FSZ];
__device__ float g_Y2[FSZ];
__device__ float g_Y3[FSZ];

// fp16 weight images: [tap][128 co][136 ci]
__device__ __half g_W0p[3*128*136];
__device__ __half g_W1p[9*128*136];
__device__ __half g_W2p[9*128*136];
__device__ __half g_W3p[1*128*136];

// per-conv-instance BN stat slots: [slot][0:128)=sum, [128:256)=ssq
#define NSLOTS 50
__device__ float g_stats[NSLOTS*256];

// ---------- helpers ----------
__device__ __forceinline__ uint32_t smem_u32(const void* p) {
    uint32_t a;
    asm("{ .reg .u64 t; cvta.to.shared.u64 t, %1; cvt.u32.u64 %0, t; }" : "=r"(a) : "l"(p));
    return a;
}
__device__ __forceinline__ void cp_async16(uint32_t dst, const void* src) {
    asm volatile("cp.async.cg.shared.global [%0], [%1], 16;" :: "r"(dst), "l"(src));
}
#define CP_COMMIT() asm volatile("cp.async.commit_group;" ::: "memory")
#define CP_WAIT(n)  asm volatile("cp.async.wait_group %0;" :: "n"(n) : "memory")

__device__ __forceinline__ void ldsm_x4(uint32_t* r, uint32_t addr) {
    asm volatile("ldmatrix.sync.aligned.m8n8.x4.shared.b16 {%0,%1,%2,%3}, [%4];"
        : "=r"(r[0]), "=r"(r[1]), "=r"(r[2]), "=r"(r[3]) : "r"(addr));
}
__device__ __forceinline__ void mma_f16(float* d, const uint32_t* a, uint32_t b0, uint32_t b1) {
    asm volatile("mma.sync.aligned.m16n8k16.row.col.f32.f16.f16.f32 "
        "{%0,%1,%2,%3}, {%4,%5,%6,%7}, {%8,%9}, {%0,%1,%2,%3};"
        : "+f"(d[0]), "+f"(d[1]), "+f"(d[2]), "+f"(d[3])
        : "r"(a[0]), "r"(a[1]), "r"(a[2]), "r"(a[3]), "r"(b0), "r"(b1));
}

// ---------- small kernels ----------
__global__ void init_stats_kernel() {
    g_stats[blockIdx.x * 256 + threadIdx.x] = 0.f;
}

// src [128 co][CIR][NK] -> img [tap][co][136] fp16
__global__ void prep_w_kernel(const float* __restrict__ src, __half* __restrict__ img,
                              int CIR, int NK) {
    int idx = blockIdx.x * 256 + threadIdx.x;
    int tot = NK * 128 * 136;
    if (idx >= tot) return;
    int tap = idx / (128 * 136);
    int rem = idx - tap * 128 * 136;
    int co = rem / 136, ci = rem - co * 136;
    float v = (ci < CIR) ? src[(co * CIR + ci) * NK + tap] : 0.f;
    img[idx] = __float2half_rn(v);
}

// x[b][80][500] -> X[b][t][c]
__global__ void xpose_kernel(const float* __restrict__ x, float* __restrict__ X) {
    int i = blockIdx.x * 256 + threadIdx.x;
    if (i >= FSZ) return;
    int c = i & 127, bt = i >> 7;
    int t = bt % TLEN, b = bt / TLEN;
    X[i] = (c < 80) ? x[(b * 80 + c) * TLEN + t] : 0.f;
}

__global__ void bn_relu_kernel(const float* __restrict__ Y, const float* __restrict__ bns,
                               float* __restrict__ Z) {
    __shared__ float ms[128], rs[128];
    int tid = threadIdx.x;
    if (tid < 128) {
        float m = bns[tid] * (1.f / NELEM);
        float v = bns[128 + tid] * (1.f / NELEM) - m * m;
        ms[tid] = m; rs[tid] = rsqrtf(v + BN_EPS);
    }
    __syncthreads();
    int i4 = blockIdx.x * 256 + tid;
    if (i4 * 4 >= FSZ) return;
    int c0 = (i4 * 4) & 127;
    float4 y = ((const float4*)Y)[i4];
    float4 o;
    o.x = fmaxf((y.x - ms[c0]) * rs[c0], 0.f);
    o.y = fmaxf((y.y - ms[c0+1]) * rs[c0+1], 0.f);
    o.z = fmaxf((y.z - ms[c0+2]) * rs[c0+2], 0.f);
    o.w = fmaxf((y.w - ms[c0+3]) * rs[c0+3], 0.f);
    ((float4*)Z)[i4] = o;
}

__global__ void combine_kernel(const float* __restrict__ Y2, const float* __restrict__ Y3,
                               const float* __restrict__ bns2, const float* __restrict__ bns3,
                               const float* __restrict__ Z, float* __restrict__ K,
                               float* __restrict__ ZA, float* __restrict__ Zout,
                               float wgt, int mode) {
    __shared__ float m2s[128], r2s[128], m3s[128], r3s[128];
    int tid = threadIdx.x;
    if (tid < 128) {
        float m = bns2[tid] * (1.f / NELEM);
        float v = bns2[128 + tid] * (1.f / NELEM) - m * m;
        m2s[tid] = m; r2s[tid] = rsqrtf(v + BN_EPS);
        m = bns3[tid] * (1.f / NELEM);
        v = bns3[128 + tid] * (1.f / NELEM) - m * m;
        m3s[tid] = m; r3s[tid] = rsqrtf(v + BN_EPS);
    }
    __syncthreads();
    int i4 = blockIdx.x * 256 + tid;
    if (i4 * 4 >= FSZ) return;
    int c0 = (i4 * 4) & 127;
    float4 y2 = ((const float4*)Y2)[i4];
    float4 y3 = ((const float4*)Y3)[i4];
    float4 kk;
    {
        float a = fmaxf((y3.x - m3s[c0]) * r3s[c0], 0.f);
        kk.x = fmaxf((y2.x - m2s[c0]) * r2s[c0] + a, 0.f);
        a = fmaxf((y3.y - m3s[c0+1]) * r3s[c0+1], 0.f);
        kk.y = fmaxf((y2.y - m2s[c0+1]) * r2s[c0+1] + a, 0.f);
        a = fmaxf((y3.z - m3s[c0+2]) * r3s[c0+2], 0.f);
        kk.z = fmaxf((y2.z - m2s[c0+2]) * r2s[c0+2] + a, 0.f);
        a = fmaxf((y3.w - m3s[c0+3]) * r3s[c0+3], 0.f);
        kk.w = fmaxf((y2.w - m2s[c0+3]) * r2s[c0+3] + a, 0.f);
    }
    ((float4*)K)[i4] = kk;
    float4 base;
    if (mode == 0) base = ((const float4*)Z)[i4];
    else           base = ((const float4*)ZA)[i4];
    float4 o;
    o.x = base.x + wgt * kk.x; o.y = base.y + wgt * kk.y;
    o.z = base.z + wgt * kk.z; o.w = base.w + wgt * kk.w;
    if (mode == 2) ((float4*)Zout)[i4] = o;
    else           ((float4*)ZA)[i4] = o;
}

__global__ void pool_head_kernel(const float* __restrict__ Z, const float* __restrict__ ow,
                                 const float* __restrict__ ob, float* __restrict__ out) {
    __shared__ float feat[128];
    int b = blockIdx.x, c = threadIdx.x;
    float s = 0.f;
    for (int t = 0; t < TLEN; t++) s += Z[((b * TLEN + t) << 7) + c];
    feat[c] = s * (1.0f / (float)TLEN);
    __syncthreads();
    if (c < NLAB) {
        float o = ob[c];
        for (int k = 0; k < 128; k++) o = fmaf(feat[k], ow[c * 128 + k], o);
        out[b * NLAB + c] = o;
    }
}

// ---------- mma.sync fp16 conv kernel ----------
// CTA tile: 64 co x 125 t (grid 4 x 2 x 128 = 1024 CTAs, occupancy 3).
#define NB      136
#define ROWB    272
#define B_OFF   0
#define A_OFF   (NB*ROWB)            // 36992
#define A_TAPB  17408                // 64 rows x 272
#define SM_STAT (A_OFF + 2*A_TAPB)   // 71808
#define SMEM_SZ (SM_STAT + 1024)     // 72832
#define A_CHUNKS (A_TAPB/16)         // 1088

// epilogue: frags -> Ts (A-buf0, two 64-row passes, stride 68) -> stores + stat atomics
__device__ __forceinline__ void epilogue_store(
    char* smem, float acc[2][4][4], int co_w, int t_w, int g, int tq,
    int tid, int b, int t0, int coBase, float* __restrict__ out, float* __restrict__ stat) {
    float* Ts = (float*)(smem + A_OFF);
    float s = 0.f, q = 0.f;
    const int c = tid & 63;
    const int ph = tid >> 6;
#pragma unroll
    for (int p = 0; p < 2; p++) {
        __syncthreads();
        if ((t_w >> 6) == p) {
#pragma unroll
            for (int mt = 0; mt < 2; mt++)
#pragma unroll
                for (int nt = 0; nt < 4; nt++) {
                    int co = co_w + mt * 16 + g;
                    int t  = (t_w & 63) + nt * 8 + tq * 2;
                    Ts[t * 68 + co]           = acc[mt][nt][0];
                    Ts[(t + 1) * 68 + co]     = acc[mt][nt][1];
                    Ts[t * 68 + co + 8]       = acc[mt][nt][2];
                    Ts[(t + 1) * 68 + co + 8] = acc[mt][nt][3];
                }
        }
        __syncthreads();
        for (int tl = ph; tl < 64; tl += 4) {
            int tt = p * 64 + tl;
            if (tt < 125) {
                float v = Ts[tl * 68 + c];
                s += v; q += v * v;
                out[((b * TLEN + t0 + tt) << 7) + coBase + c] = v;
            }
        }
    }
    atomicAdd(&stat[coBase + c], s);
    atomicAdd(&stat[128 + coBase + c], q);
}

// CTA: batch b = blockIdx.z, co-half = blockIdx.y, t-tile = blockIdx.x.
// B smem: 136 rows x 128 ci fp16 (row 272B). A (64-co weight slice) double-buffered.
// FUSE3: second 1x1 conv phase sharing staged B (W3 into A-buf1 during epilogue).
template <int NTAPS, bool FUSE3>
__global__ __launch_bounds__(256, 3)
void conv_mma_kernel(const float* __restrict__ in, const float* __restrict__ in2, float alpha,
                     const __half* __restrict__ wimg, const __half* __restrict__ w3img,
                     const float* __restrict__ bnsA,
                     float* __restrict__ out, float* __restrict__ stat,
                     float* __restrict__ out3, float* __restrict__ stat3) {
    constexpr int R = NTAPS / 2;
    extern __shared__ char smem[];
    const uint32_t sb = smem_u32(smem);
    const int tid = threadIdx.x;
    const int t0 = blockIdx.x * 125;
    const int coBase = blockIdx.y * 64;
    const int b  = blockIdx.z;

    const bool hbn = (bnsA != nullptr), h2 = (in2 != nullptr);

    float* smA_m = (float*)(smem + SM_STAT);
    float* smA_r = smA_m + 128;
    if (hbn) {
        if (tid < 128) {
            float m = bnsA[tid] * (1.f / NELEM);
            float v = bnsA[128 + tid] * (1.f / NELEM) - m * m;
            smA_m[tid] = m; smA_r[tid] = rsqrtf(v + BN_EPS);
        }
        __syncthreads();
    }

    // ---- stage B (full 128 ci) ----
    for (int idx = tid; idx < NB * 64; idx += 256) {
        int j = idx >> 6, pr = idx & 63;
        int u = t0 - R + j;
        float v0 = 0.f, v1 = 0.f;
        if (u >= 0 && u < TLEN) {
            int off = ((b * TLEN + u) << 7) + pr * 2;
            const float* p = in + off;
            v0 = p[0]; v1 = p[1];
            int c = pr * 2;
            if (hbn) {
                v0 = fmaxf((v0 - smA_m[c]) * smA_r[c], 0.f);
                v1 = fmaxf((v1 - smA_m[c + 1]) * smA_r[c + 1], 0.f);
            }
            if (h2) {
                const float* qq = in2 + off;
                v0 += alpha * qq[0]; v1 += alpha * qq[1];
            }
        }
        *(__half2*)(smem + B_OFF + j * ROWB + pr * 4) = __floats2half2_rn(v0, v1);
    }

    // weight slice base for this co-half: [tap][coBase..coBase+64)[136]
    const __half* wbase = wimg + (size_t)coBase * 136;

    // ---- prefetch A tap 0 ----
    for (int i = tid; i < A_CHUNKS; i += 256)
        cp_async16(sb + A_OFF + i * 16, (const char*)wbase + i * 16);
    CP_COMMIT();
    __syncthreads();

    // warp layout: 2 (co, 32 each) x 4 (t, 32 each)
    const int wid = tid >> 5, lane = tid & 31;
    const int co_w = (wid & 1) * 32;
    const int t_w  = (wid >> 1) * 32;
    const int g  = lane >> 2;
    const int tq = lane & 3;
    const int a_row = lane & 15;
    const int a_kh  = (lane >> 4) * 16;
    const int quad = lane >> 3;
    const int b_nl = (lane & 7) + ((quad >> 1) * 8);
    const int b_kh = (quad & 1) * 16;

    float acc[2][4][4];
#pragma unroll
    for (int mt = 0; mt < 2; mt++)
#pragma unroll
        for (int nt = 0; nt < 4; nt++)
#pragma unroll
            for (int e = 0; e < 4; e++) acc[mt][nt][e] = 0.f;

#pragma unroll 1
    for (int tap = 0; tap < NTAPS; tap++) {
        const int buf = tap & 1;
        if (tap + 1 < NTAPS) {
            const char* src = (const char*)wbase + (size_t)(tap + 1) * 128 * 136 * 2;
            uint32_t dst = sb + A_OFF + ((tap + 1) & 1) * A_TAPB;
            for (int i = tid; i < A_CHUNKS; i += 256) cp_async16(dst + i * 16, src + i * 16);
            CP_COMMIT();
            CP_WAIT(1);
        } else {
            CP_WAIT(0);
        }
        __syncthreads();

        const uint32_t Ab = sb + A_OFF + buf * A_TAPB;
        const uint32_t Bb = sb + B_OFF + (t_w + tap + b_nl) * ROWB + b_kh;

#pragma unroll
        for (int kc = 0; kc < 8; kc++) {
            uint32_t af[2][4];
#pragma unroll
            for (int mt = 0; mt < 2; mt++)
                ldsm_x4(af[mt], Ab + (co_w + mt * 16 + a_row) * ROWB + kc * 32 + a_kh);
            uint32_t bf[2][4];
#pragma unroll
            for (int p = 0; p < 2; p++)
                ldsm_x4(bf[p], Bb + p * 16 * ROWB + kc * 32);
#pragma unroll
            for (int mt = 0; mt < 2; mt++)
#pragma unroll
                for (int nt = 0; nt < 4; nt++)
                    mma_f16(acc[mt][nt], af[mt], bf[nt >> 1][(nt & 1) * 2], bf[nt >> 1][(nt & 1) * 2 + 1]);
        }
        __syncthreads();
    }

    if (FUSE3) {
        const char* src3 = (const char*)(w3img + (size_t)coBase * 136);
        for (int i = tid; i < A_CHUNKS; i += 256)
            cp_async16(sb + A_OFF + A_TAPB + i * 16, src3 + i * 16);
        CP_COMMIT();
    }

    epilogue_store(smem, acc, co_w, t_w, g, tq, tid, b, t0, coBase, out, stat);

    if (FUSE3) {
        CP_WAIT(0);
        __syncthreads();
#pragma unroll
        for (int mt = 0; mt < 2; mt++)
#pragma unroll
            for (int nt = 0; nt < 4; nt++)
#pragma unroll
                for (int e = 0; e < 4; e++) acc[mt][nt][e] = 0.f;

        const uint32_t Ab = sb + A_OFF + A_TAPB;
        const uint32_t Bb = sb + B_OFF + (t_w + R + b_nl) * ROWB + b_kh;
#pragma unroll
        for (int kc = 0; kc < 8; kc++) {
            uint32_t af[2][4];
#pragma unroll
            for (int mt = 0; mt < 2; mt++)
                ldsm_x4(af[mt], Ab + (co_w + mt * 16 + a_row) * ROWB + kc * 32 + a_kh);
            uint32_t bf[2][4];
#pragma unroll
            for (int p = 0; p < 2; p++)
                ldsm_x4(bf[p], Bb + p * 16 * ROWB + kc * 32);
#pragma unroll
            for (int mt = 0; mt < 2; mt++)
#pragma unroll
                for (int nt = 0; nt < 4; nt++)
                    mma_f16(acc[mt][nt], af[mt], bf[nt >> 1][(nt & 1) * 2], bf[nt >> 1][(nt & 1) * 2 + 1]);
        }
        epilogue_store(smem, acc, co_w, t_w, g, tq, tid, b, t0, coBase, out3, stat3);
    }
}

// ---------- launch ----------
extern "C" void kernel_launch(void* const* d_in, const int* in_sizes, int n_in,
                              void* d_out, int out_size) {
    const float* x  = (const float*)d_in[0];
    const float* w0 = (const float*)d_in[1];
    const float* w1 = (const float*)d_in[2];
    const float* w2 = (const float*)d_in[3];
    const float* w3 = (const float*)d_in[4];
    const float* ow = (const float*)d_in[5];
    const float* ob = (const float*)d_in[6];
    float* out = (float*)d_out;

    cudaFuncSetAttribute(conv_mma_kernel<9, true>,  cudaFuncAttributeMaxDynamicSharedMemorySize, SMEM_SZ);
    cudaFuncSetAttribute(conv_mma_kernel<9, false>, cudaFuncAttributeMaxDynamicSharedMemorySize, SMEM_SZ);
    cudaFuncSetAttribute(conv_mma_kernel<3, false>, cudaFuncAttributeMaxDynamicSharedMemorySize, SMEM_SZ);

    float *pX,*pZ,*pZA,*pK,*pY1,*pY2,*pY3,*pS;
    __half *pW0,*pW1,*pW2,*pW3;
    cudaGetSymbolAddress((void**)&pX,  g_X);
    cudaGetSymbolAddress((void**)&pZ,  g_Z);
    cudaGetSymbolAddress((void**)&pZA, g_ZA);
    cudaGetSymbolAddress((void**)&pK,  g_K);
    cudaGetSymbolAddress((void**)&pY1, g_Y1);
    cudaGetSymbolAddress((void**)&pY2, g_Y2);
    cudaGetSymbolAddress((void**)&pY3, g_Y3);
    cudaGetSymbolAddress((void**)&pW0, g_W0p);
    cudaGetSymbolAddress((void**)&pW1, g_W1p);
    cudaGetSymbolAddress((void**)&pW2, g_W2p);
    cudaGetSymbolAddress((void**)&pW3, g_W3p);
    cudaGetSymbolAddress((void**)&pS,  g_stats);

    const float dt = 0.25f;
    dim3 cgrid(4, 2, 128);   // t-tile x co-half x batch = 1024 CTAs
    const int EW = (FSZ + 255) / 256;
    const int EW4 = (FSZ / 4 + 255) / 256;

    init_stats_kernel<<<NSLOTS, 256>>>();
    prep_w_kernel<<<(3*128*136 + 255)/256, 256>>>(w0, pW0, 80, 3);
    prep_w_kernel<<<(9*128*136 + 255)/256, 256>>>(w1, pW1, 128, 9);
    prep_w_kernel<<<(9*128*136 + 255)/256, 256>>>(w2, pW2, 128, 9);
    prep_w_kernel<<<(1*128*136 + 255)/256, 256>>>(w3, pW3, 128, 1);
    xpose_kernel<<<EW, 256>>>(x, pX);

    // conv0 -> Y1 (+slot 0), then BN+relu -> Z
    conv_mma_kernel<3, false><<<cgrid, 256, SMEM_SZ>>>(pX, nullptr, 0.f, pW0, nullptr,
                                                       nullptr, pY1, pS, nullptr, nullptr);
    bn_relu_kernel<<<EW4, 256>>>(pY1, pS, pZ);

    for (int step = 0; step < 4; ++step) {
        for (int e = 0; e < 4; ++e) {
            float alpha = (e == 0) ? 0.f : (e == 3 ? dt : 0.5f * dt);
            const float* in2 = (e == 0) ? nullptr : (const float*)pK;
            int si = 1 + (step * 4 + e) * 3;
            float* slotA = pS + si * 256;        // conv1 (Y1) stats
            float* slotB = pS + (si + 1) * 256;  // conv3 (Y3) stats
            float* slotC = pS + (si + 2) * 256;  // conv2 (Y2) stats

            // fused conv1(9-tap) + conv3(1x1), shared staged B
            conv_mma_kernel<9, true><<<cgrid, 256, SMEM_SZ>>>(pZ, in2, alpha, pW1, pW3,
                                                              nullptr, pY1, slotA, pY3, slotB);
            // conv2 with inline BN+relu of Y1 from slotA
            conv_mma_kernel<9, false><<<cgrid, 256, SMEM_SZ>>>(pY1, nullptr, 0.f, pW2, nullptr,
                                                               slotA, pY2, slotC, nullptr, nullptr);
            float wgt = (dt / 6.0f) * ((e == 0 || e == 3) ? 1.0f : 2.0f);
            int mode = (e == 0) ? 0 : (e == 3 ? 2 : 1);
            combine_kernel<<<EW4, 256>>>(pY2, pY3, slotC, slotB, pZ, pK, pZA, pZ, wgt, mode);
        }
    }

    pool_head_kernel<<<128, 128>>>(pZ, ow, ob, out);
}